// round 2
// baseline (speedup 1.0000x reference)
#include <cuda_runtime.h>
#include <cuda_bf16.h>
#include <cstdint>

// ============================================================================
// Problem constants
// ============================================================================
static constexpr int K_DIM = 1024;
static constexpr int N_DIM = 2560;
static constexpr int M_DIM = 32 * 577;  // 18464

// GEMM tiling (mma.sync int8 path — tcgen05 unavailable: harness builds
// PTX at compute_103 (no 'a'), which rejects all tcgen05/TMEM instructions)
static constexpr int BM = 128;
static constexpr int BN = 128;
static constexpr int BK = 128;          // bytes per row per stage (int8)
static constexpr int STAGES = 3;
static constexpr int KOUT = K_DIM / BK; // 8

static constexpr int MTILES = (M_DIM + BM - 1) / BM;  // 145
static constexpr int NTILES = N_DIM / BN;             // 20

static constexpr int A_STAGE_BYTES = BM * BK;               // 16384
static constexpr int B_STAGE_BYTES = BN * BK;               // 16384
static constexpr int STAGE_BYTES = A_STAGE_BYTES + B_STAGE_BYTES;  // 32768
static constexpr int SMEM_TOTAL = STAGES * STAGE_BYTES;     // 98304

// Scratch (device globals: no allocation allowed)
__device__ __align__(16) signed char g_xq8[(size_t)M_DIM * K_DIM];
__device__ float g_sx[M_DIM];
__device__ __align__(16) signed char g_w8[(size_t)N_DIM * K_DIM];

// ============================================================================
// Helpers
// ============================================================================
__device__ __forceinline__ uint32_t smem_u32(const void* p) {
    uint32_t a;
    asm("{ .reg .u64 t; cvta.to.shared.u64 t, %1; cvt.u32.u64 %0, t; }"
        : "=r"(a) : "l"(p));
    return a;
}

// SW128 swizzle: XOR 16B-chunk index (bits 6:4) with row index (bits 9:7).
__device__ __forceinline__ uint32_t swz(uint32_t b) { return b ^ ((b >> 3) & 0x70); }

__device__ __forceinline__ void cp16(uint32_t dst, const void* src, int src_bytes) {
    asm volatile("cp.async.cg.shared.global [%0], [%1], 16, %2;"
                 :: "r"(dst), "l"(src), "r"(src_bytes) : "memory");
}
#define CP_COMMIT() asm volatile("cp.async.commit_group;" ::: "memory")
#define CP_WAIT(n) asm volatile("cp.async.wait_group %0;" :: "n"(n) : "memory")

__device__ __forceinline__ void ldsm4(uint32_t* r, uint32_t addr) {
    asm volatile("ldmatrix.sync.aligned.m8n8.x4.shared.b16 {%0,%1,%2,%3}, [%4];"
                 : "=r"(r[0]), "=r"(r[1]), "=r"(r[2]), "=r"(r[3]) : "r"(addr));
}

__device__ __forceinline__ void mma_s8(int* c, const uint32_t* a, const uint32_t* b) {
    asm volatile(
        "mma.sync.aligned.m16n8k32.row.col.s32.s8.s8.s32 "
        "{%0,%1,%2,%3}, {%4,%5,%6,%7}, {%8,%9}, {%0,%1,%2,%3};"
        : "+r"(c[0]), "+r"(c[1]), "+r"(c[2]), "+r"(c[3])
        : "r"(a[0]), "r"(a[1]), "r"(a[2]), "r"(a[3]), "r"(b[0]), "r"(b[1]));
}

__device__ __forceinline__ uint32_t pack4(float a, float b, float c, float d) {
    int ia = (int)a, ib = (int)b, ic = (int)c, id = (int)d;
    return (uint32_t)(ia & 0xFF) | ((uint32_t)(ib & 0xFF) << 8) |
           ((uint32_t)(ic & 0xFF) << 16) | ((uint32_t)(id & 0xFF) << 24);
}

// ============================================================================
// Kernel 1: per-row dynamic int8 quantization of x
// ============================================================================
__global__ __launch_bounds__(128) void quantize_kernel(const float* __restrict__ x) {
    int m = blockIdx.x;
    int t = threadIdx.x;
    const float4* xr = reinterpret_cast<const float4*>(x + (size_t)m * K_DIM);
    float4 v0 = xr[t];
    float4 v1 = xr[t + 128];

    float am = fmaxf(fmaxf(fabsf(v0.x), fabsf(v0.y)), fmaxf(fabsf(v0.z), fabsf(v0.w)));
    am = fmaxf(am, fmaxf(fmaxf(fabsf(v1.x), fabsf(v1.y)), fmaxf(fabsf(v1.z), fabsf(v1.w))));
    #pragma unroll
    for (int off = 16; off > 0; off >>= 1)
        am = fmaxf(am, __shfl_xor_sync(0xffffffffu, am, off));

    __shared__ float red[4];
    int wid = t >> 5, lid = t & 31;
    if (lid == 0) red[wid] = am;
    __syncthreads();
    am = fmaxf(fmaxf(red[0], red[1]), fmaxf(red[2], red[3]));

    // scale = max(absmax, 1e-8)/127 ; q = rint(x/scale) — matches jnp exactly
    float scale = __fdiv_rn(fmaxf(am, 1e-8f), 127.0f);
    if (t == 0) g_sx[m] = scale;

    float q0 = rintf(__fdiv_rn(v0.x, scale)), q1 = rintf(__fdiv_rn(v0.y, scale));
    float q2 = rintf(__fdiv_rn(v0.z, scale)), q3 = rintf(__fdiv_rn(v0.w, scale));
    float q4 = rintf(__fdiv_rn(v1.x, scale)), q5 = rintf(__fdiv_rn(v1.y, scale));
    float q6 = rintf(__fdiv_rn(v1.z, scale)), q7 = rintf(__fdiv_rn(v1.w, scale));

    uint32_t* row = reinterpret_cast<uint32_t*>(g_xq8 + (size_t)m * K_DIM);
    row[t] = pack4(q0, q1, q2, q3);
    row[t + 128] = pack4(q4, q5, q6, q7);
}

// ============================================================================
// Kernel 2: w_int (int32, |w|<=127) -> int8
// ============================================================================
__global__ __launch_bounds__(256) void wconv_kernel(const int* __restrict__ w) {
    size_t i = (size_t)blockIdx.x * 256 + threadIdx.x;  // int4 chunk index
    int4 v = reinterpret_cast<const int4*>(w)[i];
    reinterpret_cast<uint32_t*>(g_w8)[i] =
        (uint32_t)(v.x & 0xFF) | ((uint32_t)(v.y & 0xFF) << 8) |
        ((uint32_t)(v.z & 0xFF) << 16) | ((uint32_t)(v.w & 0xFF) << 24);
}

// ============================================================================
// Kernel 3: int8 mma.sync GEMM, 128x128x128 tiles, 3-stage cp.async pipeline
// ============================================================================
__device__ __forceinline__ void load_stage(uint32_t smem_base, int buf, int ko,
                                           int mrow0, int nrow0, int tid) {
    const uint32_t sbase = smem_base + buf * STAGE_BYTES;
    const int k0 = ko * BK;
    #pragma unroll
    for (int i = 0; i < 4; i++) {  // A: 1024 chunks of 16B
        int cid = tid + i * 256;
        int row = cid >> 3;
        int c16 = (cid & 7) * 16;
        int rg = mrow0 + row;
        const void* src = g_xq8 + (size_t)rg * K_DIM + k0 + c16;
        cp16(sbase + swz((uint32_t)row * 128u + c16), src, (rg < M_DIM) ? 16 : 0);
    }
    #pragma unroll
    for (int i = 0; i < 4; i++) {  // B: 1024 chunks
        int cid = tid + i * 256;
        int row = cid >> 3;
        int c16 = (cid & 7) * 16;
        const void* src = g_w8 + (size_t)(nrow0 + row) * K_DIM + k0 + c16;
        cp16(sbase + A_STAGE_BYTES + swz((uint32_t)row * 128u + c16), src, 16);
    }
}

__global__ __launch_bounds__(256, 2) void gemm_kernel(
    float* __restrict__ out, const float* __restrict__ scale_w,
    const float* __restrict__ bias) {
    extern __shared__ char smem[];
    const uint32_t smem_base = smem_u32(smem);
    const int tid = threadIdx.x;
    const int wid = tid >> 5;
    const int lane = tid & 31;
    const int wm = wid & 3;   // 4 warps along M -> 32 rows each
    const int wn = wid >> 2;  // 2 warps along N -> 64 cols each
    const int mrow0 = blockIdx.y * BM;
    const int nrow0 = blockIdx.x * BN;

    int c[2][8][4];
    #pragma unroll
    for (int mi = 0; mi < 2; mi++)
        #pragma unroll
        for (int ni = 0; ni < 8; ni++)
            #pragma unroll
            for (int j = 0; j < 4; j++) c[mi][ni][j] = 0;

    // ldmatrix lane address components (byte offsets within tile, pre-swizzle)
    const int lt = lane >> 3;    // tile index 0..3
    const int lr = lane & 7;     // row within tile
    // A tiles: (rowoff = (lt&1)*8, khalf = lt>>1)
    const uint32_t a_row[2] = {
        (uint32_t)(wm * 32 + 0 * 16 + (lt & 1) * 8 + lr) * 128u + (uint32_t)(lt >> 1) * 16u,
        (uint32_t)(wm * 32 + 1 * 16 + (lt & 1) * 8 + lr) * 128u + (uint32_t)(lt >> 1) * 16u};
    // B tiles: (nblock = lt>>1, khalf = lt&1)
    uint32_t b_row[4];
    #pragma unroll
    for (int p = 0; p < 4; p++)
        b_row[p] = (uint32_t)(wn * 64 + p * 16 + (lt >> 1) * 8 + lr) * 128u +
                   (uint32_t)(lt & 1) * 16u;

    // Prologue: stages 0 and 1 in flight
    load_stage(smem_base, 0, 0, mrow0, nrow0, tid);
    CP_COMMIT();
    load_stage(smem_base, 1, 1, mrow0, nrow0, tid);
    CP_COMMIT();

    for (int ko = 0; ko < KOUT; ko++) {
        if (ko + 2 < KOUT)
            load_stage(smem_base, (ko + 2) % STAGES, ko + 2, mrow0, nrow0, tid);
        CP_COMMIT();
        CP_WAIT(2);        // stage ko resident
        __syncthreads();

        const uint32_t sA = smem_base + (ko % STAGES) * STAGE_BYTES;
        const uint32_t sB = sA + A_STAGE_BYTES;

        #pragma unroll
        for (int ks = 0; ks < 4; ks++) {
            const uint32_t koff = (uint32_t)ks * 32u;
            uint32_t a[2][4], b[4][4];
            #pragma unroll
            for (int mi = 0; mi < 2; mi++) ldsm4(a[mi], sA + swz(a_row[mi] + koff));
            #pragma unroll
            for (int p = 0; p < 4; p++) ldsm4(b[p], sB + swz(b_row[p] + koff));
            #pragma unroll
            for (int mi = 0; mi < 2; mi++)
                #pragma unroll
                for (int p = 0; p < 4; p++) {
                    mma_s8(c[mi][p * 2 + 0], a[mi], &b[p][0]);
                    mma_s8(c[mi][p * 2 + 1], a[mi], &b[p][2]);
                }
        }
        __syncthreads();   // protect buffer (ko%3) before it is refilled
    }

    // Epilogue: stage scale_w/bias through smem, dequant + bias, float2 stores
    float* swsm = reinterpret_cast<float*>(smem);
    float* bsm = swsm + 128;
    if (tid < 128) {
        swsm[tid] = scale_w[nrow0 + tid];
        bsm[tid] = bias[nrow0 + tid];
    }
    __syncthreads();

    const int l4 = lane >> 2, t4 = lane & 3;
    #pragma unroll
    for (int mi = 0; mi < 2; mi++) {
        const int row0 = mrow0 + wm * 32 + mi * 16 + l4;
        const float sx0 = (row0 < M_DIM) ? g_sx[row0] : 0.0f;
        const float sx1 = (row0 + 8 < M_DIM) ? g_sx[row0 + 8] : 0.0f;
        #pragma unroll
        for (int ni = 0; ni < 8; ni++) {
            const int colL = wn * 64 + ni * 8 + 2 * t4;
            const float sw0 = swsm[colL], sw1 = swsm[colL + 1];
            const float b0 = bsm[colL], b1 = bsm[colL + 1];
            const int col = nrow0 + colL;
            if (row0 < M_DIM) {
                float2 o;
                o.x = __fadd_rn(__fmul_rn(__fmul_rn((float)c[mi][ni][0], sx0), sw0), b0);
                o.y = __fadd_rn(__fmul_rn(__fmul_rn((float)c[mi][ni][1], sx0), sw1), b1);
                *reinterpret_cast<float2*>(out + (size_t)row0 * N_DIM + col) = o;
            }
            if (row0 + 8 < M_DIM) {
                float2 o;
                o.x = __fadd_rn(__fmul_rn(__fmul_rn((float)c[mi][ni][2], sx1), sw0), b0);
                o.y = __fadd_rn(__fmul_rn(__fmul_rn((float)c[mi][ni][3], sx1), sw1), b1);
                *reinterpret_cast<float2*>(out + (size_t)(row0 + 8) * N_DIM + col) = o;
            }
        }
    }
}

// ============================================================================
// Launch
// ============================================================================
extern "C" void kernel_launch(void* const* d_in, const int* in_sizes, int n_in,
                              void* d_out, int out_size) {
    const float* x = (const float*)d_in[0];
    const int* w_int = (const int*)d_in[1];
    const float* scale_w = (const float*)d_in[2];
    const float* bias = (const float*)d_in[3];
    float* out = (float*)d_out;

    cudaFuncSetAttribute(gemm_kernel, cudaFuncAttributeMaxDynamicSharedMemorySize,
                         SMEM_TOTAL);

    quantize_kernel<<<M_DIM, 128>>>(x);
    wconv_kernel<<<(N_DIM * K_DIM) / (256 * 4), 256>>>(w_int);
    dim3 grid(NTILES, MTILES);
    gemm_kernel<<<grid, 256, SMEM_TOTAL>>>(out, scale_w, bias);
}

// round 3
// speedup vs baseline: 2.5716x; 2.5716x over previous
#include <cuda_runtime.h>
#include <cuda_bf16.h>
#include <cstdint>

// ============================================================================
// Feature gate: tcgen05/TMEM only exists on arch-specific ('a') or family
// ('f') compilation passes. On a plain compute_103 pass these macros are
// undefined and the tcgen05 kernel compiles to an empty body; the host
// detects that via cudaFuncGetAttributes and uses the mma.sync fallback.
// ============================================================================
#if defined(__CUDA_ARCH__) && (__CUDA_ARCH__ >= 1000) && \
    (defined(__CUDA_ARCH_FEAT_SM103_ALL) || defined(__CUDA_ARCH_FEAT_SM100_ALL) || \
     defined(__CUDA_ARCH_SPECIFIC__) || defined(__CUDA_ARCH_FAMILY_SPECIFIC__))
#define HAS_TC 1
#else
#define HAS_TC 0
#endif

// ============================================================================
// Problem constants
// ============================================================================
static constexpr int K_DIM = 1024;
static constexpr int N_DIM = 2560;
static constexpr int M_DIM = 32 * 577;  // 18464

// ---------------- mma.sync fallback tiling ----------------
static constexpr int BM = 128;
static constexpr int BN = 128;
static constexpr int BK = 128;
static constexpr int STAGES = 3;
static constexpr int KOUT = K_DIM / BK;               // 8
static constexpr int MTILES = (M_DIM + BM - 1) / BM;  // 145
static constexpr int NTILES = N_DIM / BN;             // 20
static constexpr int A_STAGE_BYTES = BM * BK;
static constexpr int B_STAGE_BYTES = BN * BK;
static constexpr int STAGE_BYTES = A_STAGE_BYTES + B_STAGE_BYTES;
static constexpr int SMEM_TOTAL_MMA = STAGES * STAGE_BYTES;  // 98304

// ---------------- tcgen05 tiling ----------------
static constexpr int TC_MT = 128;
static constexpr int TC_NT = 256;
static constexpr int TC_KC = 128;
static constexpr int TC_KOUT = K_DIM / TC_KC;   // 8
static constexpr int TC_KSTEPS = TC_KC / 16;    // 8 MMAs of K=16
static constexpr int TC_NTILES = N_DIM / TC_NT; // 10
// idesc: dtype=F32(1<<4), atype=BF16(1<<7), btype=BF16(1<<10), N>>3@17, M>>4@24
static constexpr uint32_t TC_IDESC =
    (1u << 4) | (1u << 7) | (1u << 10) | ((TC_NT / 8) << 17) | ((TC_MT / 16) << 24);
static constexpr int TC_SMEM_TMEM_PTR = 0;
static constexpr int TC_SMEM_MBAR = 8;  // two 8B mbarriers at +8, +16
static constexpr int TC_A_BYTES = TC_MT * TC_KC * 2;  // 32768
static constexpr int TC_B_BYTES = TC_NT * TC_KC * 2;  // 65536
static constexpr int TC_STAGE_BYTES = TC_A_BYTES + TC_B_BYTES;  // 98304
static constexpr int TC_SMEM_A0 = 1024;
static constexpr int TC_SMEM_B0 = TC_SMEM_A0 + TC_A_BYTES;
static constexpr int SMEM_TOTAL_TC = TC_SMEM_A0 + 2 * TC_STAGE_BYTES;  // 197632
static constexpr int TMEM_COLS = 256;

// ============================================================================
// Scratch (device globals: no allocation allowed)
// ============================================================================
__device__ __align__(16) signed char g_xq8[(size_t)M_DIM * K_DIM];
__device__ __align__(16) signed char g_w8[(size_t)N_DIM * K_DIM];
__device__ __align__(16) __nv_bfloat16 g_xqb[(size_t)M_DIM * K_DIM];
__device__ __align__(16) __nv_bfloat16 g_wb[(size_t)N_DIM * K_DIM];
__device__ float g_sx[M_DIM];

// ============================================================================
// Common helpers
// ============================================================================
__device__ __forceinline__ uint32_t smem_u32(const void* p) {
    uint32_t a;
    asm("{ .reg .u64 t; cvta.to.shared.u64 t, %1; cvt.u32.u64 %0, t; }"
        : "=r"(a) : "l"(p));
    return a;
}
__device__ __forceinline__ uint32_t swz(uint32_t b) { return b ^ ((b >> 3) & 0x70); }

__device__ __forceinline__ void cp16(uint32_t dst, const void* src, int src_bytes) {
    asm volatile("cp.async.cg.shared.global [%0], [%1], 16, %2;"
                 :: "r"(dst), "l"(src), "r"(src_bytes) : "memory");
}
#define CP_COMMIT() asm volatile("cp.async.commit_group;" ::: "memory")
#define CP_WAIT(n) asm volatile("cp.async.wait_group %0;" :: "n"(n) : "memory")

__device__ __forceinline__ void ldsm4(uint32_t* r, uint32_t addr) {
    asm volatile("ldmatrix.sync.aligned.m8n8.x4.shared.b16 {%0,%1,%2,%3}, [%4];"
                 : "=r"(r[0]), "=r"(r[1]), "=r"(r[2]), "=r"(r[3]) : "r"(addr));
}
__device__ __forceinline__ void mma_s8(int* c, const uint32_t* a, const uint32_t* b) {
    asm volatile(
        "mma.sync.aligned.m16n8k32.row.col.s32.s8.s8.s32 "
        "{%0,%1,%2,%3}, {%4,%5,%6,%7}, {%8,%9}, {%0,%1,%2,%3};"
        : "+r"(c[0]), "+r"(c[1]), "+r"(c[2]), "+r"(c[3])
        : "r"(a[0]), "r"(a[1]), "r"(a[2]), "r"(a[3]), "r"(b[0]), "r"(b[1]));
}
__device__ __forceinline__ uint32_t pack4i(float a, float b, float c, float d) {
    int ia = (int)a, ib = (int)b, ic = (int)c, id = (int)d;
    return (uint32_t)(ia & 0xFF) | ((uint32_t)(ib & 0xFF) << 8) |
           ((uint32_t)(ic & 0xFF) << 16) | ((uint32_t)(id & 0xFF) << 24);
}
__device__ __forceinline__ uint32_t pack_bf16x2(float a, float b) {
    __nv_bfloat162 h;
    h.x = __float2bfloat16_rn(a);
    h.y = __float2bfloat16_rn(b);
    return *reinterpret_cast<uint32_t*>(&h);
}

// ============================================================================
// Quantize kernels: per-row absmax -> scale, q = rint(x/scale)
// ============================================================================
template <int OUT_BF16>
__global__ __launch_bounds__(128) void quantize_kernel(const float* __restrict__ x) {
    int m = blockIdx.x;
    int t = threadIdx.x;
    const float4* xr = reinterpret_cast<const float4*>(x + (size_t)m * K_DIM);
    float4 v0 = xr[t];
    float4 v1 = xr[t + 128];

    float am = fmaxf(fmaxf(fabsf(v0.x), fabsf(v0.y)), fmaxf(fabsf(v0.z), fabsf(v0.w)));
    am = fmaxf(am, fmaxf(fmaxf(fabsf(v1.x), fabsf(v1.y)), fmaxf(fabsf(v1.z), fabsf(v1.w))));
    #pragma unroll
    for (int off = 16; off > 0; off >>= 1)
        am = fmaxf(am, __shfl_xor_sync(0xffffffffu, am, off));

    __shared__ float red[4];
    int wid = t >> 5, lid = t & 31;
    if (lid == 0) red[wid] = am;
    __syncthreads();
    am = fmaxf(fmaxf(red[0], red[1]), fmaxf(red[2], red[3]));

    float scale = __fdiv_rn(fmaxf(am, 1e-8f), 127.0f);
    if (t == 0) g_sx[m] = scale;

    float q0 = rintf(__fdiv_rn(v0.x, scale)), q1 = rintf(__fdiv_rn(v0.y, scale));
    float q2 = rintf(__fdiv_rn(v0.z, scale)), q3 = rintf(__fdiv_rn(v0.w, scale));
    float q4 = rintf(__fdiv_rn(v1.x, scale)), q5 = rintf(__fdiv_rn(v1.y, scale));
    float q6 = rintf(__fdiv_rn(v1.z, scale)), q7 = rintf(__fdiv_rn(v1.w, scale));

    if (OUT_BF16) {
        __nv_bfloat16* row = g_xqb + (size_t)m * K_DIM;
        uint2 p0, p1;
        p0.x = pack_bf16x2(q0, q1); p0.y = pack_bf16x2(q2, q3);
        p1.x = pack_bf16x2(q4, q5); p1.y = pack_bf16x2(q6, q7);
        *reinterpret_cast<uint2*>(row + t * 4) = p0;
        *reinterpret_cast<uint2*>(row + 512 + t * 4) = p1;
    } else {
        uint32_t* row = reinterpret_cast<uint32_t*>(g_xq8 + (size_t)m * K_DIM);
        row[t] = pack4i(q0, q1, q2, q3);
        row[t + 128] = pack4i(q4, q5, q6, q7);
    }
}

template <int OUT_BF16>
__global__ __launch_bounds__(256) void wconv_kernel(const int* __restrict__ w) {
    size_t i = (size_t)blockIdx.x * 256 + threadIdx.x;  // int4 chunk index
    int4 v = reinterpret_cast<const int4*>(w)[i];
    if (OUT_BF16) {
        uint2 o;
        o.x = pack_bf16x2((float)v.x, (float)v.y);
        o.y = pack_bf16x2((float)v.z, (float)v.w);
        *reinterpret_cast<uint2*>(g_wb + i * 4) = o;
    } else {
        reinterpret_cast<uint32_t*>(g_w8)[i] =
            (uint32_t)(v.x & 0xFF) | ((uint32_t)(v.y & 0xFF) << 8) |
            ((uint32_t)(v.z & 0xFF) << 16) | ((uint32_t)(v.w & 0xFF) << 24);
    }
}

// ============================================================================
// Fallback GEMM: int8 mma.sync, 128x128x128 tiles, 3-stage cp.async (R2 kernel)
// ============================================================================
__device__ __forceinline__ void load_stage_mma(uint32_t smem_base, int buf, int ko,
                                               int mrow0, int nrow0, int tid) {
    const uint32_t sbase = smem_base + buf * STAGE_BYTES;
    const int k0 = ko * BK;
    #pragma unroll
    for (int i = 0; i < 4; i++) {
        int cid = tid + i * 256;
        int row = cid >> 3;
        int c16 = (cid & 7) * 16;
        int rg = mrow0 + row;
        const void* src = g_xq8 + (size_t)rg * K_DIM + k0 + c16;
        cp16(sbase + swz((uint32_t)row * 128u + c16), src, (rg < M_DIM) ? 16 : 0);
    }
    #pragma unroll
    for (int i = 0; i < 4; i++) {
        int cid = tid + i * 256;
        int row = cid >> 3;
        int c16 = (cid & 7) * 16;
        const void* src = g_w8 + (size_t)(nrow0 + row) * K_DIM + k0 + c16;
        cp16(sbase + A_STAGE_BYTES + swz((uint32_t)row * 128u + c16), src, 16);
    }
}

__global__ __launch_bounds__(256, 2) void gemm_mma(
    float* __restrict__ out, const float* __restrict__ scale_w,
    const float* __restrict__ bias) {
    extern __shared__ char smem[];
    const uint32_t smem_base = smem_u32(smem);
    const int tid = threadIdx.x;
    const int wid = tid >> 5;
    const int lane = tid & 31;
    const int wm = wid & 3;
    const int wn = wid >> 2;
    const int mrow0 = blockIdx.y * BM;
    const int nrow0 = blockIdx.x * BN;

    int c[2][8][4];
    #pragma unroll
    for (int mi = 0; mi < 2; mi++)
        #pragma unroll
        for (int ni = 0; ni < 8; ni++)
            #pragma unroll
            for (int j = 0; j < 4; j++) c[mi][ni][j] = 0;

    const int lt = lane >> 3;
    const int lr = lane & 7;
    const uint32_t a_row[2] = {
        (uint32_t)(wm * 32 + 0 * 16 + (lt & 1) * 8 + lr) * 128u + (uint32_t)(lt >> 1) * 16u,
        (uint32_t)(wm * 32 + 1 * 16 + (lt & 1) * 8 + lr) * 128u + (uint32_t)(lt >> 1) * 16u};
    uint32_t b_row[4];
    #pragma unroll
    for (int p = 0; p < 4; p++)
        b_row[p] = (uint32_t)(wn * 64 + p * 16 + (lt >> 1) * 8 + lr) * 128u +
                   (uint32_t)(lt & 1) * 16u;

    load_stage_mma(smem_base, 0, 0, mrow0, nrow0, tid);
    CP_COMMIT();
    load_stage_mma(smem_base, 1, 1, mrow0, nrow0, tid);
    CP_COMMIT();

    for (int ko = 0; ko < KOUT; ko++) {
        if (ko + 2 < KOUT)
            load_stage_mma(smem_base, (ko + 2) % STAGES, ko + 2, mrow0, nrow0, tid);
        CP_COMMIT();
        CP_WAIT(2);
        __syncthreads();

        const uint32_t sA = smem_base + (ko % STAGES) * STAGE_BYTES;
        const uint32_t sB = sA + A_STAGE_BYTES;

        #pragma unroll
        for (int ks = 0; ks < 4; ks++) {
            const uint32_t koff = (uint32_t)ks * 32u;
            uint32_t a[2][4], b[4][4];
            #pragma unroll
            for (int mi = 0; mi < 2; mi++) ldsm4(a[mi], sA + swz(a_row[mi] + koff));
            #pragma unroll
            for (int p = 0; p < 4; p++) ldsm4(b[p], sB + swz(b_row[p] + koff));
            #pragma unroll
            for (int mi = 0; mi < 2; mi++)
                #pragma unroll
                for (int p = 0; p < 4; p++) {
                    mma_s8(c[mi][p * 2 + 0], a[mi], &b[p][0]);
                    mma_s8(c[mi][p * 2 + 1], a[mi], &b[p][2]);
                }
        }
        __syncthreads();
    }

    float* swsm = reinterpret_cast<float*>(smem);
    float* bsm = swsm + 128;
    if (tid < 128) {
        swsm[tid] = scale_w[nrow0 + tid];
        bsm[tid] = bias[nrow0 + tid];
    }
    __syncthreads();

    const int l4 = lane >> 2, t4 = lane & 3;
    #pragma unroll
    for (int mi = 0; mi < 2; mi++) {
        const int row0 = mrow0 + wm * 32 + mi * 16 + l4;
        const float sx0 = (row0 < M_DIM) ? g_sx[row0] : 0.0f;
        const float sx1 = (row0 + 8 < M_DIM) ? g_sx[row0 + 8] : 0.0f;
        #pragma unroll
        for (int ni = 0; ni < 8; ni++) {
            const int colL = wn * 64 + ni * 8 + 2 * t4;
            const float sw0 = swsm[colL], sw1 = swsm[colL + 1];
            const float b0 = bsm[colL], b1 = bsm[colL + 1];
            const int col = nrow0 + colL;
            if (row0 < M_DIM) {
                float2 o;
                o.x = __fadd_rn(__fmul_rn(__fmul_rn((float)c[mi][ni][0], sx0), sw0), b0);
                o.y = __fadd_rn(__fmul_rn(__fmul_rn((float)c[mi][ni][1], sx0), sw1), b1);
                *reinterpret_cast<float2*>(out + (size_t)row0 * N_DIM + col) = o;
            }
            if (row0 + 8 < M_DIM) {
                float2 o;
                o.x = __fadd_rn(__fmul_rn(__fmul_rn((float)c[mi][ni][2], sx1), sw0), b0);
                o.y = __fadd_rn(__fmul_rn(__fmul_rn((float)c[mi][ni][3], sx1), sw1), b1);
                *reinterpret_cast<float2*>(out + (size_t)(row0 + 8) * N_DIM + col) = o;
            }
        }
    }
}

// ============================================================================
// tcgen05 GEMM (bf16 SS, MT=128 x NT=256, double-buffered K stages).
// Entire body feature-gated: empty on non-'a' compilation passes.
// ============================================================================
#if HAS_TC
#define TC_ALLOC(smem_addr, n) \
    asm volatile("tcgen05.alloc.cta_group::1.sync.aligned.shared::cta.b32 [%0], %1;" \
                 :: "r"(smem_addr), "r"((uint32_t)(n)) : "memory")
#define TC_DEALLOC(tmem, n) \
    asm volatile("tcgen05.dealloc.cta_group::1.sync.aligned.b32 %0, %1;" \
                 :: "r"(tmem), "r"((uint32_t)(n)))
#define TC_RELINQ() \
    asm volatile("tcgen05.relinquish_alloc_permit.cta_group::1.sync.aligned;")
#define TC_COMMIT(mbar) \
    asm volatile("tcgen05.commit.cta_group::1.mbarrier::arrive::one.shared::cluster.b64 [%0];" \
                 :: "r"(mbar) : "memory")
#define TC_FENCE_AFTER() asm volatile("tcgen05.fence::after_thread_sync;" ::: "memory")
#define TC_FENCE_BEFORE() asm volatile("tcgen05.fence::before_thread_sync;" ::: "memory")
#define TC_WAIT_LD() asm volatile("tcgen05.wait::ld.sync.aligned;" ::: "memory")
#define FENCE_ASYNC_SHARED() asm volatile("fence.proxy.async.shared::cta;" ::: "memory")
#define MBAR_INIT(addr, cnt) \
    asm volatile("mbarrier.init.shared.b64 [%0], %1;" :: "r"(addr), "r"((uint32_t)(cnt)) : "memory")

__device__ __forceinline__ uint32_t elect_one() {
    uint32_t pred;
    asm volatile(
        "{\n\t.reg .pred p;\n\t"
        "elect.sync _|p, 0xFFFFFFFF;\n\t"
        "selp.b32 %0, 1, 0, p;\n\t}"
        : "=r"(pred));
    return pred;
}
__device__ __forceinline__ void mbar_wait_acq(uint32_t addr, uint32_t parity) {
    uint32_t done;
    do {
        asm volatile(
            "{\n\t.reg .pred p;\n\t"
            "mbarrier.try_wait.parity.acquire.cta.shared::cta.b64 p, [%1], %2, 0x989680;\n\t"
            "selp.b32 %0, 1, 0, p;\n\t}"
            : "=r"(done) : "r"(addr), "r"(parity) : "memory");
    } while (!done);
}
__device__ __forceinline__ void mma_f16_ss(uint32_t d_tmem, uint64_t a_desc,
                                           uint64_t b_desc, uint32_t idesc,
                                           uint32_t enable_d) {
    asm volatile(
        "{\n\t.reg .pred p;\n\t"
        "setp.ne.u32 p, %5, 0;\n\t"
        "tcgen05.mma.cta_group::1.kind::f16 [%0], %1, %2, %3, {%4, %4, %4, %4}, p;\n\t"
        "}"
        :: "r"(d_tmem), "l"(a_desc), "l"(b_desc), "r"(idesc), "r"(0u), "r"(enable_d)
        : "memory");
}
#define TC_LD_X32(r, tmem) \
    asm volatile( \
        "tcgen05.ld.sync.aligned.32x32b.x32.b32 " \
        "{%0, %1, %2, %3, %4, %5, %6, %7, " \
        " %8, %9, %10, %11, %12, %13, %14, %15, " \
        " %16, %17, %18, %19, %20, %21, %22, %23, " \
        " %24, %25, %26, %27, %28, %29, %30, %31}, [%32];" \
        : "=r"((r)[0]),  "=r"((r)[1]),  "=r"((r)[2]),  "=r"((r)[3]), \
          "=r"((r)[4]),  "=r"((r)[5]),  "=r"((r)[6]),  "=r"((r)[7]), \
          "=r"((r)[8]),  "=r"((r)[9]),  "=r"((r)[10]), "=r"((r)[11]), \
          "=r"((r)[12]), "=r"((r)[13]), "=r"((r)[14]), "=r"((r)[15]), \
          "=r"((r)[16]), "=r"((r)[17]), "=r"((r)[18]), "=r"((r)[19]), \
          "=r"((r)[20]), "=r"((r)[21]), "=r"((r)[22]), "=r"((r)[23]), \
          "=r"((r)[24]), "=r"((r)[25]), "=r"((r)[26]), "=r"((r)[27]), \
          "=r"((r)[28]), "=r"((r)[29]), "=r"((r)[30]), "=r"((r)[31]) \
        : "r"(tmem))

// SW128 desc: layout=2, version=1, SBO=64 (1024B per 8-row group), LBO=1
static constexpr uint64_t DESC_BASE_SW128 =
    (2ull << 61) | (1ull << 46) | (64ull << 32) | (1ull << 16);
__device__ __forceinline__ uint64_t make_desc(uint32_t smem_addr) {
    return DESC_BASE_SW128 | ((uint64_t)(smem_addr >> 4) & 0x3FFF);
}
#endif  // HAS_TC

__global__ __launch_bounds__(256, 1) __cluster_dims__(1, 1, 1)
void gemm_tc(float* __restrict__ out, const float* __restrict__ scale_w,
             const float* __restrict__ bias) {
#if HAS_TC
    extern __shared__ char smem[];
    const uint32_t smem_base = smem_u32(smem);
    const int tid = threadIdx.x;
    const int wid = tid >> 5;
    const int lid = tid & 31;
    const int mrow0 = blockIdx.y * TC_MT;
    const int nrow0 = blockIdx.x * TC_NT;

    if (wid == 0) {
        TC_ALLOC(smem_base + TC_SMEM_TMEM_PTR, TMEM_COLS);
        TC_RELINQ();
    }
    if (tid == 0) {
        MBAR_INIT(smem_base + TC_SMEM_MBAR + 0, 1);
        MBAR_INIT(smem_base + TC_SMEM_MBAR + 8, 1);
        FENCE_ASYNC_SHARED();
    }
    __syncthreads();
    uint32_t tmem_base;
    asm volatile("ld.shared.b32 %0, [%1];" : "=r"(tmem_base)
                 : "r"(smem_base + TC_SMEM_TMEM_PTR));

    for (int ko = 0; ko < TC_KOUT; ko++) {
        const int buf = ko & 1;
        const uint32_t baseA = TC_SMEM_A0 + buf * TC_STAGE_BYTES;
        const uint32_t baseB = TC_SMEM_B0 + buf * TC_STAGE_BYTES;
        const int k0 = ko * TC_KC;

        // wait for MMA of stage ko-2 (same buffer) before overwriting
        if (ko >= 2) mbar_wait_acq(smem_base + TC_SMEM_MBAR + buf * 8, ((ko - 2) >> 1) & 1);

        // A tile: 128 rows x 128 bf16 in SW128 blocked atoms (16 atom-rows/col)
        #pragma unroll
        for (int i = 0; i < 8; i++) {
            int cid = tid + i * 256;
            int row = cid >> 4;
            int cc = (cid & 15) * 8;
            int rg = mrow0 + row;
            uint4 v = make_uint4(0u, 0u, 0u, 0u);
            if (rg < M_DIM)
                v = *reinterpret_cast<const uint4*>(g_xqb + (size_t)rg * K_DIM + k0 + cc);
            int atom = (row >> 3) + ((cc >> 6) << 4);
            uint32_t byte = (uint32_t)atom * 1024u + (row & 7) * 128u + (cc & 63) * 2u;
            *reinterpret_cast<uint4*>(smem + baseA + swz(byte)) = v;
        }
        // B tile: 256 rows x 128 bf16 (32 atom-rows/col)
        #pragma unroll
        for (int i = 0; i < 16; i++) {
            int cid = tid + i * 256;
            int row = cid >> 4;
            int cc = (cid & 15) * 8;
            uint4 v = *reinterpret_cast<const uint4*>(
                g_wb + (size_t)(nrow0 + row) * K_DIM + k0 + cc);
            int atom = (row >> 3) + ((cc >> 6) << 5);
            uint32_t byte = (uint32_t)atom * 1024u + (row & 7) * 128u + (cc & 63) * 2u;
            *reinterpret_cast<uint4*>(smem + baseB + swz(byte)) = v;
        }
        FENCE_ASYNC_SHARED();
        __syncthreads();

        if (wid == 0) {
            uint64_t adesc = make_desc(smem_base + baseA);
            uint64_t bdesc = make_desc(smem_base + baseB);
            if (elect_one()) {
                #pragma unroll
                for (int ks = 0; ks < TC_KSTEPS; ks++) {
                    // desc offsets in 16B units: +2 per K16 within atom-col;
                    // atom-col stride = num_atom_rows * 64 units
                    uint64_t ao = adesc + (uint64_t)((ks >> 2) * 1024 + (ks & 3) * 2);
                    uint64_t bo = bdesc + (uint64_t)((ks >> 2) * 2048 + (ks & 3) * 2);
                    mma_f16_ss(tmem_base, ao, bo, TC_IDESC, (ko > 0 || ks > 0) ? 1u : 0u);
                }
                TC_COMMIT(smem_base + TC_SMEM_MBAR + buf * 8);
            }
        }
    }

    // drain: each buffer got 4 commits -> wait 4th completion (parity 1)
    mbar_wait_acq(smem_base + TC_SMEM_MBAR + 0, 1);
    mbar_wait_acq(smem_base + TC_SMEM_MBAR + 8, 1);
    TC_FENCE_AFTER();

    // epilogue: warp w -> lanes (w&3)*32+lid, col half (w>>2)*128
    const int sub = wid & 3;
    const int half = wid >> 2;
    const int mg = mrow0 + sub * 32 + lid;
    const float sxv = (mg < M_DIM) ? g_sx[mg] : 0.0f;

    #pragma unroll
    for (int seg = 0; seg < 4; seg++) {
        const int col0 = half * 128 + seg * 32;
        uint32_t r[32];
        TC_LD_X32(r, tmem_base + col0);
        TC_WAIT_LD();
        if (mg < M_DIM) {
            const int cg0 = nrow0 + col0;
            float* orow = out + (size_t)mg * N_DIM + cg0;
            #pragma unroll
            for (int j4 = 0; j4 < 8; j4++) {
                float4 o;
                float a0 = __uint_as_float(r[j4 * 4 + 0]);
                float a1 = __uint_as_float(r[j4 * 4 + 1]);
                float a2 = __uint_as_float(r[j4 * 4 + 2]);
                float a3 = __uint_as_float(r[j4 * 4 + 3]);
                o.x = __fadd_rn(__fmul_rn(__fmul_rn(a0, sxv), scale_w[cg0 + j4 * 4 + 0]), bias[cg0 + j4 * 4 + 0]);
                o.y = __fadd_rn(__fmul_rn(__fmul_rn(a1, sxv), scale_w[cg0 + j4 * 4 + 1]), bias[cg0 + j4 * 4 + 1]);
                o.z = __fadd_rn(__fmul_rn(__fmul_rn(a2, sxv), scale_w[cg0 + j4 * 4 + 2]), bias[cg0 + j4 * 4 + 2]);
                o.w = __fadd_rn(__fmul_rn(__fmul_rn(a3, sxv), scale_w[cg0 + j4 * 4 + 3]), bias[cg0 + j4 * 4 + 3]);
                *reinterpret_cast<float4*>(orow + j4 * 4) = o;
            }
        }
    }
    TC_FENCE_BEFORE();
    __syncthreads();
    if (wid == 0) TC_DEALLOC(tmem_base, TMEM_COLS);
#endif  // HAS_TC
}

// ============================================================================
// Launch: pick path by probing whether the tcgen05 body actually compiled
// ============================================================================
extern "C" void kernel_launch(void* const* d_in, const int* in_sizes, int n_in,
                              void* d_out, int out_size) {
    const float* x = (const float*)d_in[0];
    const int* w_int = (const int*)d_in[1];
    const float* scale_w = (const float*)d_in[2];
    const float* bias = (const float*)d_in[3];
    float* out = (float*)d_out;

    static int path = -1;
    if (path < 0) {
        cudaFuncAttributes fa{};
        path = 0;
        if (cudaFuncGetAttributes(&fa, gemm_tc) == cudaSuccess && fa.numRegs > 40)
            path = 1;  // real tcgen05 body present
        cudaFuncSetAttribute(gemm_mma, cudaFuncAttributeMaxDynamicSharedMemorySize,
                             SMEM_TOTAL_MMA);
        if (path)
            cudaFuncSetAttribute(gemm_tc, cudaFuncAttributeMaxDynamicSharedMemorySize,
                                 SMEM_TOTAL_TC);
    }

    if (path) {
        quantize_kernel<1><<<M_DIM, 128>>>(x);
        wconv_kernel<1><<<(N_DIM * K_DIM) / (256 * 4), 256>>>(w_int);
        dim3 grid(TC_NTILES, MTILES);
        gemm_tc<<<grid, 256, SMEM_TOTAL_TC>>>(out, scale_w, bias);
    } else {
        quantize_kernel<0><<<M_DIM, 128>>>(x);
        wconv_kernel<0><<<(N_DIM * K_DIM) / (256 * 4), 256>>>(w_int);
        dim3 grid(NTILES, MTILES);
        gemm_mma<<<grid, 256, SMEM_TOTAL_MMA>>>(out, scale_w, bias);
    }
}

// round 7
// speedup vs baseline: 3.5138x; 1.3664x over previous
#include <cuda_runtime.h>
#include <cuda_bf16.h>
#include <cstdint>

// ============================================================================
// Feature gate: tcgen05/TMEM only on arch-specific ('a') / family passes.
// R3/R4 confirmed: the bench compiles this file at compute_103a, macros set.
// NOTE (R4): kind::i8 is NOT supported on sm_103a — only kind::f16 path here.
// ============================================================================
#if defined(__CUDA_ARCH__) && (__CUDA_ARCH__ >= 1000) && \
    (defined(__CUDA_ARCH_FEAT_SM103_ALL) || defined(__CUDA_ARCH_FEAT_SM100_ALL) || \
     defined(__CUDA_ARCH_SPECIFIC__) || defined(__CUDA_ARCH_FAMILY_SPECIFIC__))
#define HAS_TC 1
#else
#define HAS_TC 0
#endif

// ============================================================================
// Problem constants
// ============================================================================
static constexpr int K_DIM = 1024;
static constexpr int N_DIM = 2560;
static constexpr int M_DIM = 32 * 577;  // 18464

// ---------------- mma.sync fallback tiling (unchanged R2 kernel) ------------
static constexpr int BM = 128;
static constexpr int BN = 128;
static constexpr int BK = 128;
static constexpr int STAGES = 3;
static constexpr int KOUT = K_DIM / BK;               // 8
static constexpr int FB_MTILES = (M_DIM + BM - 1) / BM;  // 145
static constexpr int FB_NTILES = N_DIM / BN;             // 20
static constexpr int A_STAGE_BYTES = BM * BK;
static constexpr int B_STAGE_BYTES = BN * BK;
static constexpr int STAGE_BYTES = A_STAGE_BYTES + B_STAGE_BYTES;
static constexpr int SMEM_TOTAL_MMA = STAGES * STAGE_BYTES;  // 98304

// ---------------- tcgen05 bf16 tiling: 256(M) x 256(N), KC=64 ---------------
static constexpr int TC_MT = 256;                 // per CTA (2 x 128 sub-tiles)
static constexpr int TC_NT = 256;
static constexpr int TC_KC = 64;                  // bf16 elements per stage (128B row)
static constexpr int TC_SOUT = K_DIM / TC_KC;     // 16 stages
static constexpr int TC_KSTEPS = TC_KC / 16;      // 4 MMAs of K=16 per sub-tile
static constexpr int TC_NBUF = 3;
static constexpr int TC_MTILES = (M_DIM + TC_MT - 1) / TC_MT;  // 73
static constexpr int TC_NTILES = N_DIM / TC_NT;                // 10
// idesc (kind::f16): dtype=F32(1<<4), atype=BF16(1<<7), btype=BF16(1<<10),
// N>>3 @ 17, M>>4 @ 24  (M=128 per MMA)
static constexpr uint32_t TC_IDESC =
    (1u << 4) | (1u << 7) | (1u << 10) | ((TC_NT / 8) << 17) | ((128 / 16) << 24);
static constexpr int TC_SMEM_TMEM_PTR = 0;
static constexpr int TC_SMEM_MBAR = 8;            // 3 mbarriers @ +8..+32
static constexpr int TC_A_BYTES = 128 * TC_KC * 2;   // 16384 per sub-tile
static constexpr int TC_B_BYTES = TC_NT * TC_KC * 2; // 32768
static constexpr int TC_STAGE_BYTES = 2 * TC_A_BYTES + TC_B_BYTES;  // 65536
static constexpr int TC_SMEM_T0 = 1024;
static constexpr int SMEM_TOTAL_TC = TC_SMEM_T0 + TC_NBUF * TC_STAGE_BYTES;  // 197632
static constexpr int TMEM_COLS = 512;             // two 256-col accumulators

// ============================================================================
// Scratch (device globals: no allocation allowed)
// ============================================================================
__device__ __align__(16) signed char g_xq8[(size_t)M_DIM * K_DIM];
__device__ __align__(16) signed char g_w8[(size_t)N_DIM * K_DIM];
__device__ __align__(16) __nv_bfloat16 g_xqb[(size_t)M_DIM * K_DIM];
__device__ __align__(16) __nv_bfloat16 g_wb[(size_t)N_DIM * K_DIM];
__device__ float g_sx[M_DIM];

// ============================================================================
// Common helpers
// ============================================================================
__device__ __forceinline__ uint32_t smem_u32(const void* p) {
    uint32_t a;
    asm("{ .reg .u64 t; cvta.to.shared.u64 t, %1; cvt.u32.u64 %0, t; }"
        : "=r"(a) : "l"(p));
    return a;
}
__device__ __forceinline__ uint32_t swz(uint32_t b) { return b ^ ((b >> 3) & 0x70); }

__device__ __forceinline__ void cp16(uint32_t dst, const void* src, int src_bytes) {
    asm volatile("cp.async.cg.shared.global [%0], [%1], 16, %2;"
                 :: "r"(dst), "l"(src), "r"(src_bytes) : "memory");
}
#define CP_COMMIT() asm volatile("cp.async.commit_group;" ::: "memory")
#define CP_WAIT(n) asm volatile("cp.async.wait_group %0;" :: "n"(n) : "memory")

__device__ __forceinline__ void ldsm4(uint32_t* r, uint32_t addr) {
    asm volatile("ldmatrix.sync.aligned.m8n8.x4.shared.b16 {%0,%1,%2,%3}, [%4];"
                 : "=r"(r[0]), "=r"(r[1]), "=r"(r[2]), "=r"(r[3]) : "r"(addr));
}
__device__ __forceinline__ void mma_s8(int* c, const uint32_t* a, const uint32_t* b) {
    asm volatile(
        "mma.sync.aligned.m16n8k32.row.col.s32.s8.s8.s32 "
        "{%0,%1,%2,%3}, {%4,%5,%6,%7}, {%8,%9}, {%0,%1,%2,%3};"
        : "+r"(c[0]), "+r"(c[1]), "+r"(c[2]), "+r"(c[3])
        : "r"(a[0]), "r"(a[1]), "r"(a[2]), "r"(a[3]), "r"(b[0]), "r"(b[1]));
}
__device__ __forceinline__ uint32_t pack4i(float a, float b, float c, float d) {
    int ia = (int)a, ib = (int)b, ic = (int)c, id = (int)d;
    return (uint32_t)(ia & 0xFF) | ((uint32_t)(ib & 0xFF) << 8) |
           ((uint32_t)(ic & 0xFF) << 16) | ((uint32_t)(id & 0xFF) << 24);
}
__device__ __forceinline__ uint32_t pack_bf16x2(float a, float b) {
    __nv_bfloat162 h;
    h.x = __float2bfloat16_rn(a);
    h.y = __float2bfloat16_rn(b);
    return *reinterpret_cast<uint32_t*>(&h);
}

// ============================================================================
// Kernel 1: per-row dynamic int8 quantization of x
// ============================================================================
template <int OUT_BF16>
__global__ __launch_bounds__(128) void quantize_kernel(const float* __restrict__ x) {
    int m = blockIdx.x;
    int t = threadIdx.x;
    const float4* xr = reinterpret_cast<const float4*>(x + (size_t)m * K_DIM);
    float4 v0 = xr[t];
    float4 v1 = xr[t + 128];

    float am = fmaxf(fmaxf(fabsf(v0.x), fabsf(v0.y)), fmaxf(fabsf(v0.z), fabsf(v0.w)));
    am = fmaxf(am, fmaxf(fmaxf(fabsf(v1.x), fabsf(v1.y)), fmaxf(fabsf(v1.z), fabsf(v1.w))));
    #pragma unroll
    for (int off = 16; off > 0; off >>= 1)
        am = fmaxf(am, __shfl_xor_sync(0xffffffffu, am, off));

    __shared__ float red[4];
    int wid = t >> 5, lid = t & 31;
    if (lid == 0) red[wid] = am;
    __syncthreads();
    am = fmaxf(fmaxf(red[0], red[1]), fmaxf(red[2], red[3]));

    float scale = __fdiv_rn(fmaxf(am, 1e-8f), 127.0f);
    if (t == 0) g_sx[m] = scale;

    float q0 = rintf(__fdiv_rn(v0.x, scale)), q1 = rintf(__fdiv_rn(v0.y, scale));
    float q2 = rintf(__fdiv_rn(v0.z, scale)), q3 = rintf(__fdiv_rn(v0.w, scale));
    float q4 = rintf(__fdiv_rn(v1.x, scale)), q5 = rintf(__fdiv_rn(v1.y, scale));
    float q6 = rintf(__fdiv_rn(v1.z, scale)), q7 = rintf(__fdiv_rn(v1.w, scale));

    if (OUT_BF16) {
        __nv_bfloat16* row = g_xqb + (size_t)m * K_DIM;
        uint2 p0, p1;
        p0.x = pack_bf16x2(q0, q1); p0.y = pack_bf16x2(q2, q3);
        p1.x = pack_bf16x2(q4, q5); p1.y = pack_bf16x2(q6, q7);
        *reinterpret_cast<uint2*>(row + t * 4) = p0;
        *reinterpret_cast<uint2*>(row + 512 + t * 4) = p1;
    } else {
        uint32_t* row = reinterpret_cast<uint32_t*>(g_xq8 + (size_t)m * K_DIM);
        row[t] = pack4i(q0, q1, q2, q3);
        row[t + 128] = pack4i(q4, q5, q6, q7);
    }
}

// ============================================================================
// Kernel 2: w_int (int32, |w|<=127) -> bf16 / int8
// ============================================================================
template <int OUT_BF16>
__global__ __launch_bounds__(256) void wconv_kernel(const int* __restrict__ w) {
    size_t i = (size_t)blockIdx.x * 256 + threadIdx.x;  // int4 chunk index
    int4 v = reinterpret_cast<const int4*>(w)[i];
    if (OUT_BF16) {
        uint2 o;
        o.x = pack_bf16x2((float)v.x, (float)v.y);
        o.y = pack_bf16x2((float)v.z, (float)v.w);
        *reinterpret_cast<uint2*>(g_wb + i * 4) = o;
    } else {
        reinterpret_cast<uint32_t*>(g_w8)[i] =
            (uint32_t)(v.x & 0xFF) | ((uint32_t)(v.y & 0xFF) << 8) |
            ((uint32_t)(v.z & 0xFF) << 16) | ((uint32_t)(v.w & 0xFF) << 24);
    }
}

// ============================================================================
// Fallback GEMM: int8 mma.sync (known-good R2 kernel)
// ============================================================================
__device__ __forceinline__ void load_stage_mma(uint32_t smem_base, int buf, int ko,
                                               int mrow0, int nrow0, int tid) {
    const uint32_t sbase = smem_base + buf * STAGE_BYTES;
    const int k0 = ko * BK;
    #pragma unroll
    for (int i = 0; i < 4; i++) {
        int cid = tid + i * 256;
        int row = cid >> 3;
        int c16 = (cid & 7) * 16;
        int rg = mrow0 + row;
        const void* src = g_xq8 + (size_t)rg * K_DIM + k0 + c16;
        cp16(sbase + swz((uint32_t)row * 128u + c16), src, (rg < M_DIM) ? 16 : 0);
    }
    #pragma unroll
    for (int i = 0; i < 4; i++) {
        int cid = tid + i * 256;
        int row = cid >> 3;
        int c16 = (cid & 7) * 16;
        const void* src = g_w8 + (size_t)(nrow0 + row) * K_DIM + k0 + c16;
        cp16(sbase + A_STAGE_BYTES + swz((uint32_t)row * 128u + c16), src, 16);
    }
}

__global__ __launch_bounds__(256, 2) void gemm_mma(
    float* __restrict__ out, const float* __restrict__ scale_w,
    const float* __restrict__ bias) {
    extern __shared__ char smem[];
    const uint32_t smem_base = smem_u32(smem);
    const int tid = threadIdx.x;
    const int wid = tid >> 5;
    const int lane = tid & 31;
    const int wm = wid & 3;
    const int wn = wid >> 2;
    const int mrow0 = blockIdx.y * BM;
    const int nrow0 = blockIdx.x * BN;

    int c[2][8][4];
    #pragma unroll
    for (int mi = 0; mi < 2; mi++)
        #pragma unroll
        for (int ni = 0; ni < 8; ni++)
            #pragma unroll
            for (int j = 0; j < 4; j++) c[mi][ni][j] = 0;

    const int lt = lane >> 3;
    const int lr = lane & 7;
    const uint32_t a_row[2] = {
        (uint32_t)(wm * 32 + 0 * 16 + (lt & 1) * 8 + lr) * 128u + (uint32_t)(lt >> 1) * 16u,
        (uint32_t)(wm * 32 + 1 * 16 + (lt & 1) * 8 + lr) * 128u + (uint32_t)(lt >> 1) * 16u};
    uint32_t b_row[4];
    #pragma unroll
    for (int p = 0; p < 4; p++)
        b_row[p] = (uint32_t)(wn * 64 + p * 16 + (lt >> 1) * 8 + lr) * 128u +
                   (uint32_t)(lt & 1) * 16u;

    load_stage_mma(smem_base, 0, 0, mrow0, nrow0, tid);
    CP_COMMIT();
    load_stage_mma(smem_base, 1, 1, mrow0, nrow0, tid);
    CP_COMMIT();

    for (int ko = 0; ko < KOUT; ko++) {
        if (ko + 2 < KOUT)
            load_stage_mma(smem_base, (ko + 2) % STAGES, ko + 2, mrow0, nrow0, tid);
        CP_COMMIT();
        CP_WAIT(2);
        __syncthreads();

        const uint32_t sA = smem_base + (ko % STAGES) * STAGE_BYTES;
        const uint32_t sB = sA + A_STAGE_BYTES;

        #pragma unroll
        for (int ks = 0; ks < 4; ks++) {
            const uint32_t koff = (uint32_t)ks * 32u;
            uint32_t a[2][4], b[4][4];
            #pragma unroll
            for (int mi = 0; mi < 2; mi++) ldsm4(a[mi], sA + swz(a_row[mi] + koff));
            #pragma unroll
            for (int p = 0; p < 4; p++) ldsm4(b[p], sB + swz(b_row[p] + koff));
            #pragma unroll
            for (int mi = 0; mi < 2; mi++)
                #pragma unroll
                for (int p = 0; p < 4; p++) {
                    mma_s8(c[mi][p * 2 + 0], a[mi], &b[p][0]);
                    mma_s8(c[mi][p * 2 + 1], a[mi], &b[p][2]);
                }
        }
        __syncthreads();
    }

    float* swsm = reinterpret_cast<float*>(smem);
    float* bsm = swsm + 128;
    if (tid < 128) {
        swsm[tid] = scale_w[nrow0 + tid];
        bsm[tid] = bias[nrow0 + tid];
    }
    __syncthreads();

    const int l4 = lane >> 2, t4 = lane & 3;
    #pragma unroll
    for (int mi = 0; mi < 2; mi++) {
        const int row0 = mrow0 + wm * 32 + mi * 16 + l4;
        const float sx0 = (row0 < M_DIM) ? g_sx[row0] : 0.0f;
        const float sx1 = (row0 + 8 < M_DIM) ? g_sx[row0 + 8] : 0.0f;
        #pragma unroll
        for (int ni = 0; ni < 8; ni++) {
            const int colL = wn * 64 + ni * 8 + 2 * t4;
            const float sw0 = swsm[colL], sw1 = swsm[colL + 1];
            const float b0 = bsm[colL], b1 = bsm[colL + 1];
            const int col = nrow0 + colL;
            if (row0 < M_DIM) {
                float2 o;
                o.x = __fadd_rn(__fmul_rn(__fmul_rn((float)c[mi][ni][0], sx0), sw0), b0);
                o.y = __fadd_rn(__fmul_rn(__fmul_rn((float)c[mi][ni][1], sx0), sw1), b1);
                *reinterpret_cast<float2*>(out + (size_t)row0 * N_DIM + col) = o;
            }
            if (row0 + 8 < M_DIM) {
                float2 o;
                o.x = __fadd_rn(__fmul_rn(__fmul_rn((float)c[mi][ni][2], sx1), sw0), b0);
                o.y = __fadd_rn(__fmul_rn(__fmul_rn((float)c[mi][ni][3], sx1), sw1), b1);
                *reinterpret_cast<float2*>(out + (size_t)(row0 + 8) * N_DIM + col) = o;
            }
        }
    }
}

// ============================================================================
// tcgen05 bf16 GEMM: 256(M) x 256(N) per CTA, KC=64, cp.async 3-deep pipeline,
// two TMEM accumulators sharing each B tile.
// ============================================================================
#if HAS_TC
#define TC_ALLOC(smem_addr, n) \
    asm volatile("tcgen05.alloc.cta_group::1.sync.aligned.shared::cta.b32 [%0], %1;" \
                 :: "r"(smem_addr), "r"((uint32_t)(n)) : "memory")
#define TC_DEALLOC(tmem, n) \
    asm volatile("tcgen05.dealloc.cta_group::1.sync.aligned.b32 %0, %1;" \
                 :: "r"(tmem), "r"((uint32_t)(n)))
#define TC_RELINQ() \
    asm volatile("tcgen05.relinquish_alloc_permit.cta_group::1.sync.aligned;")
#define TC_COMMIT(mbar) \
    asm volatile("tcgen05.commit.cta_group::1.mbarrier::arrive::one.shared::cluster.b64 [%0];" \
                 :: "r"(mbar) : "memory")
#define TC_FENCE_AFTER() asm volatile("tcgen05.fence::after_thread_sync;" ::: "memory")
#define TC_FENCE_BEFORE() asm volatile("tcgen05.fence::before_thread_sync;" ::: "memory")
#define TC_WAIT_LD() asm volatile("tcgen05.wait::ld.sync.aligned;" ::: "memory")
#define FENCE_ASYNC_SHARED() asm volatile("fence.proxy.async.shared::cta;" ::: "memory")
#define MBAR_INIT(addr, cnt) \
    asm volatile("mbarrier.init.shared.b64 [%0], %1;" :: "r"(addr), "r"((uint32_t)(cnt)) : "memory")

__device__ __forceinline__ uint32_t elect_one() {
    uint32_t pred;
    asm volatile(
        "{\n\t.reg .pred p;\n\t"
        "elect.sync _|p, 0xFFFFFFFF;\n\t"
        "selp.b32 %0, 1, 0, p;\n\t}"
        : "=r"(pred));
    return pred;
}
__device__ __forceinline__ void mbar_wait_acq(uint32_t addr, uint32_t parity) {
    uint32_t done;
    do {
        asm volatile(
            "{\n\t.reg .pred p;\n\t"
            "mbarrier.try_wait.parity.acquire.cta.shared::cta.b64 p, [%1], %2, 0x989680;\n\t"
            "selp.b32 %0, 1, 0, p;\n\t}"
            : "=r"(done) : "r"(addr), "r"(parity) : "memory");
    } while (!done);
}
__device__ __forceinline__ void mma_f16_ss(uint32_t d_tmem, uint64_t a_desc,
                                           uint64_t b_desc, uint32_t idesc,
                                           uint32_t enable_d) {
    asm volatile(
        "{\n\t.reg .pred p;\n\t"
        "setp.ne.u32 p, %5, 0;\n\t"
        "tcgen05.mma.cta_group::1.kind::f16 [%0], %1, %2, %3, {%4, %4, %4, %4}, p;\n\t"
        "}"
        :: "r"(d_tmem), "l"(a_desc), "l"(b_desc), "r"(idesc), "r"(0u), "r"(enable_d)
        : "memory");
}
#define TC_LD_X32(r, tmem) \
    asm volatile( \
        "tcgen05.ld.sync.aligned.32x32b.x32.b32 " \
        "{%0, %1, %2, %3, %4, %5, %6, %7, " \
        " %8, %9, %10, %11, %12, %13, %14, %15, " \
        " %16, %17, %18, %19, %20, %21, %22, %23, " \
        " %24, %25, %26, %27, %28, %29, %30, %31}, [%32];" \
        : "=r"((r)[0]),  "=r"((r)[1]),  "=r"((r)[2]),  "=r"((r)[3]), \
          "=r"((r)[4]),  "=r"((r)[5]),  "=r"((r)[6]),  "=r"((r)[7]), \
          "=r"((r)[8]),  "=r"((r)[9]),  "=r"((r)[10]), "=r"((r)[11]), \
          "=r"((r)[12]), "=r"((r)[13]), "=r"((r)[14]), "=r"((r)[15]), \
          "=r"((r)[16]), "=r"((r)[17]), "=r"((r)[18]), "=r"((r)[19]), \
          "=r"((r)[20]), "=r"((r)[21]), "=r"((r)[22]), "=r"((r)[23]), \
          "=r"((r)[24]), "=r"((r)[25]), "=r"((r)[26]), "=r"((r)[27]), \
          "=r"((r)[28]), "=r"((r)[29]), "=r"((r)[30]), "=r"((r)[31]) \
        : "r"(tmem))

// SW128 K-major desc: layout=2, version=1, SBO=64 (1024B per 8-row group), LBO=1
static constexpr uint64_t DESC_BASE_SW128 =
    (2ull << 61) | (1ull << 46) | (64ull << 32) | (1ull << 16);
__device__ __forceinline__ uint64_t make_desc(uint32_t smem_addr) {
    return DESC_BASE_SW128 | ((uint64_t)(smem_addr >> 4) & 0x3FFF);
}

// Load one K stage: A0 (128x64 bf16), A1 (128x64), B (256x64). Every row is
// 128 bytes = one SW128 atom = 8 chunks of 16B.
// Chunk map (4096 total): [0,1024) A0, [1024,2048) A1, [2048,4096) B.
// (R5 postmortem: the old map used 4 chunks/row and overran B by 512 rows.)
__device__ __forceinline__ void load_stage_tc(uint32_t smem_base, int buf, int ko,
                                              int mrow0, int nrow0, int tid) {
    const uint32_t sbase = smem_base + TC_SMEM_T0 + buf * TC_STAGE_BYTES;
    const size_t k0b = (size_t)ko * TC_KC * 2;  // byte offset along K
    const signed char* xb = reinterpret_cast<const signed char*>(g_xqb);
    const signed char* wb = reinterpret_cast<const signed char*>(g_wb);
    #pragma unroll
    for (int i = 0; i < 16; i++) {
        int cid = tid + i * 256;
        if (cid < 1024) {            // A0: row = cid/8, 8 x 16B per 128B row
            int row = cid >> 3;
            int c16 = (cid & 7) * 16;
            int rg = mrow0 + row;
            const void* src = xb + (size_t)rg * (K_DIM * 2) + k0b + c16;
            cp16(sbase + swz((uint32_t)row * 128u + c16), src, (rg < M_DIM) ? 16 : 0);
        } else if (cid < 2048) {     // A1
            int idx = cid - 1024;
            int row = idx >> 3;
            int c16 = (idx & 7) * 16;
            int rg = mrow0 + 128 + row;
            const void* src = xb + (size_t)rg * (K_DIM * 2) + k0b + c16;
            cp16(sbase + TC_A_BYTES + swz((uint32_t)row * 128u + c16), src,
                 (rg < M_DIM) ? 16 : 0);
        } else {                     // B: 256 rows x 8 chunks
            int idx = cid - 2048;
            int row = idx >> 3;
            int c16 = (idx & 7) * 16;
            const void* src = wb + (size_t)(nrow0 + row) * (K_DIM * 2) + k0b + c16;
            cp16(sbase + 2 * TC_A_BYTES + swz((uint32_t)row * 128u + c16), src, 16);
        }
    }
}
#endif  // HAS_TC

__global__ __launch_bounds__(256, 1) __cluster_dims__(1, 1, 1)
void gemm_tc(float* __restrict__ out, const float* __restrict__ scale_w,
             const float* __restrict__ bias) {
#if HAS_TC
    extern __shared__ char smem[];
    const uint32_t smem_base = smem_u32(smem);
    const int tid = threadIdx.x;
    const int wid = tid >> 5;
    const int lid = tid & 31;
    const int mrow0 = blockIdx.y * TC_MT;
    const int nrow0 = blockIdx.x * TC_NT;

    if (wid == 0) {
        TC_ALLOC(smem_base + TC_SMEM_TMEM_PTR, TMEM_COLS);
        TC_RELINQ();
    }
    if (tid == 0) {
        #pragma unroll
        for (int b = 0; b < TC_NBUF; b++)
            MBAR_INIT(smem_base + TC_SMEM_MBAR + b * 8, 1);
        FENCE_ASYNC_SHARED();
    }
    __syncthreads();
    uint32_t tmem_base;
    asm volatile("ld.shared.b32 %0, [%1];" : "=r"(tmem_base)
                 : "r"(smem_base + TC_SMEM_TMEM_PTR));
    const uint32_t tmem_d0 = tmem_base;
    const uint32_t tmem_d1 = tmem_base + 256;

    // Prologue: stages 0..2 in flight (one commit group each)
    #pragma unroll
    for (int s = 0; s < TC_NBUF; s++) {
        load_stage_tc(smem_base, s, s, mrow0, nrow0, tid);
        CP_COMMIT();
    }

    for (int ko = 0; ko < TC_SOUT; ko++) {
        CP_WAIT(2);          // stage ko's cp.async group complete
        __syncthreads();
        FENCE_ASYNC_SHARED();

        const int buf = ko % TC_NBUF;
        if (wid == 0) {
            const uint32_t sbase = smem_base + TC_SMEM_T0 + buf * TC_STAGE_BYTES;
            uint64_t a0 = make_desc(sbase);
            uint64_t a1 = make_desc(sbase + TC_A_BYTES);
            uint64_t bd = make_desc(sbase + 2 * TC_A_BYTES);
            if (elect_one()) {
                #pragma unroll
                for (int ks = 0; ks < TC_KSTEPS; ks++)
                    mma_f16_ss(tmem_d0, a0 + ks * 2, bd + ks * 2, TC_IDESC,
                               (ko > 0 || ks > 0) ? 1u : 0u);
                #pragma unroll
                for (int ks = 0; ks < TC_KSTEPS; ks++)
                    mma_f16_ss(tmem_d1, a1 + ks * 2, bd + ks * 2, TC_IDESC,
                               (ko > 0 || ks > 0) ? 1u : 0u);
                TC_COMMIT(smem_base + TC_SMEM_MBAR + buf * 8);
            }
        }

        if (ko + TC_NBUF < TC_SOUT) {
            // stage ko+3 reuses buffer of stage ko: wait that MMA's commit.
            // completion ordinal on this mbar = ko/3 -> parity (ko/3)&1
            mbar_wait_acq(smem_base + TC_SMEM_MBAR + buf * 8, (ko / TC_NBUF) & 1);
            load_stage_tc(smem_base, buf, ko + TC_NBUF, mrow0, nrow0, tid);
        }
        CP_COMMIT();         // uniform group accounting each iteration
    }

    // Drain: completions per mbar: buf0 x6 (last ordinal 5 -> parity 1),
    // buf1 x5 (ordinal 4 -> 0), buf2 x5 (ordinal 4 -> 0)
    mbar_wait_acq(smem_base + TC_SMEM_MBAR + 0, 1);
    mbar_wait_acq(smem_base + TC_SMEM_MBAR + 8, 0);
    mbar_wait_acq(smem_base + TC_SMEM_MBAR + 16, 0);
    TC_FENCE_AFTER();
    __syncthreads();

    // Stage scale_w/bias through smem (tiles no longer needed)
    float* swsm = reinterpret_cast<float*>(smem + TC_SMEM_T0);
    float* bsm = swsm + TC_NT;
    swsm[tid] = scale_w[nrow0 + tid];
    bsm[tid] = bias[nrow0 + tid];
    __syncthreads();

    // Epilogue: for each accumulator, warp w -> rows (w&3)*32+lid,
    // col half (w>>2)*128, 4 segs of 32 cols
    const int sub = wid & 3;
    const int half = wid >> 2;
    #pragma unroll
    for (int acc = 0; acc < 2; acc++) {
        const uint32_t tm = acc ? tmem_d1 : tmem_d0;
        const int mg = mrow0 + acc * 128 + sub * 32 + lid;
        const float sxv = (mg < M_DIM) ? g_sx[mg] : 0.0f;
        #pragma unroll
        for (int seg = 0; seg < 4; seg++) {
            const int col0 = half * 128 + seg * 32;
            uint32_t r[32];
            TC_LD_X32(r, tm + col0);
            TC_WAIT_LD();
            if (mg < M_DIM) {
                float* orow = out + (size_t)mg * N_DIM + nrow0 + col0;
                #pragma unroll
                for (int j4 = 0; j4 < 8; j4++) {
                    float4 o;
                    const int cl = col0 + j4 * 4;
                    float a0 = __uint_as_float(r[j4 * 4 + 0]);
                    float a1 = __uint_as_float(r[j4 * 4 + 1]);
                    float a2 = __uint_as_float(r[j4 * 4 + 2]);
                    float a3 = __uint_as_float(r[j4 * 4 + 3]);
                    o.x = __fadd_rn(__fmul_rn(__fmul_rn(a0, sxv), swsm[cl + 0]), bsm[cl + 0]);
                    o.y = __fadd_rn(__fmul_rn(__fmul_rn(a1, sxv), swsm[cl + 1]), bsm[cl + 1]);
                    o.z = __fadd_rn(__fmul_rn(__fmul_rn(a2, sxv), swsm[cl + 2]), bsm[cl + 2]);
                    o.w = __fadd_rn(__fmul_rn(__fmul_rn(a3, sxv), swsm[cl + 3]), bsm[cl + 3]);
                    *reinterpret_cast<float4*>(orow + j4 * 4) = o;
                }
            }
        }
    }
    TC_FENCE_BEFORE();
    __syncthreads();
    if (wid == 0) TC_DEALLOC(tmem_base, TMEM_COLS);
#endif  // HAS_TC
}

// ============================================================================
// Launch: pick path by probing whether the tcgen05 body actually compiled
// ============================================================================
extern "C" void kernel_launch(void* const* d_in, const int* in_sizes, int n_in,
                              void* d_out, int out_size) {
    const float* x = (const float*)d_in[0];
    const int* w_int = (const int*)d_in[1];
    const float* scale_w = (const float*)d_in[2];
    const float* bias = (const float*)d_in[3];
    float* out = (float*)d_out;

    static int path = -1;
    if (path < 0) {
        cudaFuncAttributes fa{};
        path = 0;
        if (cudaFuncGetAttributes(&fa, gemm_tc) == cudaSuccess && fa.numRegs > 40)
            path = 1;  // real tcgen05 body present
        cudaFuncSetAttribute(gemm_mma, cudaFuncAttributeMaxDynamicSharedMemorySize,
                             SMEM_TOTAL_MMA);
        if (path)
            cudaFuncSetAttribute(gemm_tc, cudaFuncAttributeMaxDynamicSharedMemorySize,
                                 SMEM_TOTAL_TC);
    }

    if (path) {
        quantize_kernel<1><<<M_DIM, 128>>>(x);
        wconv_kernel<1><<<(N_DIM * K_DIM) / (256 * 4), 256>>>(w_int);
        dim3 grid(TC_NTILES, TC_MTILES);
        gemm_tc<<<grid, 256, SMEM_TOTAL_TC>>>(out, scale_w, bias);
    } else {
        quantize_kernel<0><<<M_DIM, 128>>>(x);
        wconv_kernel<0><<<(N_DIM * K_DIM) / (256 * 4), 256>>>(w_int);
        dim3 grid(FB_NTILES, FB_MTILES);
        gemm_mma<<<grid, 256, SMEM_TOTAL_MMA>>>(out, scale_w, bias);
    }
}